// round 2
// baseline (speedup 1.0000x reference)
#include <cuda_runtime.h>
#include <cuda_bf16.h>
#include <math.h>

#define B_      8
#define H_      16
#define DIM_    2048
#define QLR_    1536
#define KVLR_   512
#define DN_     128
#define DR_     64
#define DV_     128
#define STARTP  8191
#define TTOT    8192
#define NSPLIT  36
#define CHUNK   228     // ceil(8192/36)
#define TTOK    8
#define EPS_    1e-6f
#define SCALE_  0.07216878364870323f   // (128+64)^-0.5

// ---------------- scratch (__device__ globals; no allocations) ----------------
__device__ __align__(16) float g_kvpe [B_*576];
__device__ __align__(16) float g_qraw [B_*QLR_];
__device__ __align__(16) float g_qa   [B_*QLR_];
__device__ __align__(16) float g_q    [B_*3072];
__device__ __align__(16) float g_qabs [B_*H_*KVLR_];
__device__ __align__(16) float g_qpe  [B_*H_*DR_];
__device__ __align__(16) float g_kvnew[B_*KVLR_];
__device__ __align__(16) float g_kpenew[B_*DR_];
__device__ __align__(16) float g_pout [(size_t)B_*NSPLIT*H_*KVLR_];
__device__ __align__(16) float g_pml  [B_*NSPLIT*H_*2];
__device__ __align__(16) float g_ctx  [B_*H_*KVLR_];
__device__ __align__(16) float g_ctxv [B_*DIM_];

// ---------------- packed fp32x2 helpers ----------------
__device__ __forceinline__ void fma2(unsigned long long& d, unsigned long long a, unsigned long long b) {
    asm("fma.rn.f32x2 %0, %1, %2, %0;" : "+l"(d) : "l"(a), "l"(b));
}
__device__ __forceinline__ unsigned long long mul2(unsigned long long a, unsigned long long b) {
    unsigned long long r;
    asm("mul.rn.f32x2 %0, %1, %2;" : "=l"(r) : "l"(a), "l"(b));
    return r;
}
__device__ __forceinline__ float2 u2f(unsigned long long v) {
    float2 r;
    asm("mov.b64 {%0,%1}, %2;" : "=f"(r.x), "=f"(r.y) : "l"(v));
    return r;
}
__device__ __forceinline__ unsigned long long f2u(float a, float b) {
    unsigned long long r;
    asm("mov.b64 %0, {%1,%2};" : "=l"(r) : "f"(a), "f"(b));
    return r;
}

// ---------------- batched (8-way) matvec: Y[b][r] = W[r,:].X[b,:] + bias[r] ----------------
// One warp = one row, all 8 batches. Weights streamed once from HBM; X stays L1-resident.
__global__ void matvec8(const float* __restrict__ W, const float* __restrict__ bias,
                        const float* __restrict__ Xext, float* __restrict__ Yext,
                        int xsel, int ysel, int R, int C) {
    const float* X = (xsel == 1) ? g_qa : (xsel == 2) ? g_ctxv : Xext;
    float* Y = (ysel == 1) ? g_kvpe : (ysel == 2) ? g_qraw : (ysel == 3) ? g_q : Yext;
    int w = threadIdx.x >> 5, lane = threadIdx.x & 31;
    int r = blockIdx.x * 8 + w;
    if (r >= R) return;
    int C4 = C >> 2;
    const ulonglong2* w2 = ((const ulonglong2*)W) + (size_t)r * C4;
    const ulonglong2* x2 = (const ulonglong2*)X;
    unsigned long long a0[B_], a1[B_];
    #pragma unroll
    for (int b = 0; b < B_; b++) { a0[b] = 0ull; a1[b] = 0ull; }
    for (int j = lane; j < C4; j += 32) {
        ulonglong2 wv = __ldg(w2 + j);
        #pragma unroll
        for (int b = 0; b < B_; b++) {
            ulonglong2 xv = __ldg(x2 + b * C4 + j);
            fma2(a0[b], wv.x, xv.x);
            fma2(a1[b], wv.y, xv.y);
        }
    }
    float bs = bias[r];
    #pragma unroll
    for (int b = 0; b < B_; b++) {
        float2 f0 = u2f(a0[b]), f1 = u2f(a1[b]);
        float s = (f0.x + f0.y) + (f1.x + f1.y);
        #pragma unroll
        for (int off = 16; off; off >>= 1) s += __shfl_xor_sync(0xffffffffu, s, off);
        if (lane == 0) Y[(size_t)b * R + r] = s + bs;
    }
}

// ---------------- block-wide sum reduce (<=256 threads) ----------------
__device__ __forceinline__ float block_sum(float v, float* red) {
    int w = threadIdx.x >> 5, lane = threadIdx.x & 31;
    #pragma unroll
    for (int off = 16; off; off >>= 1) v += __shfl_xor_sync(0xffffffffu, v, off);
    if (lane == 0) red[w] = v;
    __syncthreads();
    if (threadIdx.x < 32) {
        int nw = blockDim.x >> 5;
        float t = (threadIdx.x < nw) ? red[threadIdx.x] : 0.f;
        #pragma unroll
        for (int off = 4; off; off >>= 1) t += __shfl_xor_sync(0xffffffffu, t, off);
        if (threadIdx.x == 0) red[0] = t;
    }
    __syncthreads();
    return red[0];
}

// ---------------- rms of q_a (N=1536) ----------------
__global__ void rmsq_kernel(const float* __restrict__ qnw) {
    __shared__ float red[8];
    int b = blockIdx.x;
    const float* x = g_qraw + b * QLR_;
    float ss = 0.f;
    for (int i = threadIdx.x; i < QLR_; i += blockDim.x) { float v = x[i]; ss += v * v; }
    float tot = block_sum(ss, red);
    float sc = rsqrtf(tot / QLR_ + EPS_);
    for (int i = threadIdx.x; i < QLR_; i += blockDim.x)
        g_qa[b * QLR_ + i] = x[i] * qnw[i] * sc;
}

// ---------------- kv rms + k_pe rope ----------------
__global__ void kvprep_kernel(const float* __restrict__ kvnw,
                              const float* __restrict__ cosv, const float* __restrict__ sinv) {
    __shared__ float red[8];
    int b = blockIdx.x;
    const float* kvpe = g_kvpe + b * 576;
    float ss = 0.f;
    for (int i = threadIdx.x; i < KVLR_; i += blockDim.x) { float v = kvpe[i]; ss += v * v; }
    float tot = block_sum(ss, red);
    float sc = rsqrtf(tot / KVLR_ + EPS_);
    for (int i = threadIdx.x; i < KVLR_; i += blockDim.x)
        g_kvnew[b * KVLR_ + i] = kvpe[i] * kvnw[i] * sc;
    if (threadIdx.x < 32) {
        int j = threadIdx.x;
        float xr = kvpe[KVLR_ + 2 * j], xi = kvpe[KVLR_ + 2 * j + 1];
        float c = cosv[j], s = sinv[j];
        g_kpenew[b * DR_ + 2 * j]     = xr * c - xi * s;
        g_kpenew[b * DR_ + 2 * j + 1] = xr * s + xi * c;
    }
}

// ---------------- q absorption (q_abs = q_nope @ W_uk) + q_pe rope ----------------
__global__ void qprep_kernel(const float* __restrict__ wkvb,
                             const float* __restrict__ cosv, const float* __restrict__ sinv) {
    __shared__ float qn[DN_];
    int h = blockIdx.x, b = blockIdx.y, tid = threadIdx.x;
    const float* qsrc = g_q + b * 3072 + h * (DN_ + DR_);
    if (tid < DN_) {
        qn[tid] = qsrc[tid];
    } else if (tid < DN_ + 32) {
        int j = tid - DN_;
        float xr = qsrc[DN_ + 2 * j], xi = qsrc[DN_ + 2 * j + 1];
        float c = cosv[j], s = sinv[j];
        g_qpe[(b * H_ + h) * DR_ + 2 * j]     = xr * c - xi * s;
        g_qpe[(b * H_ + h) * DR_ + 2 * j + 1] = xr * s + xi * c;
    }
    __syncthreads();
    int c = tid;  // 512 threads
    const float* W = wkvb + (size_t)h * 256 * KVLR_ + c;
    float a = 0.f;
    #pragma unroll 8
    for (int d = 0; d < DN_; d++) a = fmaf(qn[d], W[(size_t)d * KVLR_], a);
    g_qabs[(b * H_ + h) * KVLR_ + c] = a;
}

// ---------------- fused flash-decode attention (split-KV partials) ----------------
// block = 128 thr = 4 warps; warp handles 4 heads; lane = (head_local[2b], slice[3b]).
// Slice s owns float4 indices {s + 8*i} of the 144-float4 (kv|pe) row -> conflict-free
// LDS.128 with 4-way broadcast. Everything packed f32x2.
__global__ void __launch_bounds__(128, 2) attn_kernel(const float* __restrict__ kvpre,
                                                      const float* __restrict__ pepre) {
    __shared__ __align__(16) float4 tile[2][TTOK][144];
    int b = blockIdx.y, split = blockIdx.x;
    int t0 = split * CHUNK;
    int t1 = min(t0 + CHUNK, TTOT);
    int tid = threadIdx.x, w = tid >> 5, lane = tid & 31;
    int hl = lane >> 3, s = lane & 7;
    int head = w * 4 + hl;

    ulonglong2 q[18];
    {
        const ulonglong2* qa = (const ulonglong2*)(g_qabs + (size_t)(b * H_ + head) * KVLR_);
        #pragma unroll
        for (int i = 0; i < 16; i++) q[i] = qa[s + 8 * i];
        const ulonglong2* qp = (const ulonglong2*)(g_qpe + (size_t)(b * H_ + head) * DR_);
        q[16] = qp[s];
        q[17] = qp[s + 8];
    }
    unsigned long long acc[32];
    #pragma unroll
    for (int i = 0; i < 32; i++) acc[i] = 0ull;
    float m = -INFINITY, l = 0.f;

    const float4* kv4  = (const float4*)kvpre;
    const float4* pe4  = (const float4*)pepre;
    const float4* kvn4 = (const float4*)g_kvnew;
    const float4* pen4 = (const float4*)g_kpenew;

    int ntiles = (t1 - t0 + TTOK - 1) / TTOK;

    auto issue_tile = [&](int buf, int ti) {
        int tb = t0 + ti * TTOK;
        int cnt = min(TTOK, t1 - tb);
        for (int idx = tid; idx < cnt * 144; idx += 128) {
            int tk = idx / 144, j = idx - tk * 144;
            int t = tb + tk;
            const float4* src;
            if (j < 128)
                src = (t < STARTP) ? (kv4 + ((size_t)b * STARTP + t) * 128 + j)
                                   : (kvn4 + b * 128 + j);
            else
                src = (t < STARTP) ? (pe4 + ((size_t)b * STARTP + t) * 16 + (j - 128))
                                   : (pen4 + b * 16 + (j - 128));
            unsigned sa = (unsigned)__cvta_generic_to_shared(&tile[buf][tk][j]);
            asm volatile("cp.async.cg.shared.global [%0], [%1], 16;\n" :: "r"(sa), "l"(src));
        }
        asm volatile("cp.async.commit_group;\n");
    };

    issue_tile(0, 0);
    for (int ti = 0; ti < ntiles; ti++) {
        if (ti + 1 < ntiles) {
            issue_tile((ti + 1) & 1, ti + 1);
            asm volatile("cp.async.wait_group 1;\n");
        } else {
            asm volatile("cp.async.wait_group 0;\n");
        }
        __syncthreads();
        int tb = t0 + ti * TTOK;
        int cnt = min(TTOK, t1 - tb);
        const float4 (*tl)[144] = tile[ti & 1];
        for (int tk = 0; tk < cnt; tk++) {
            const ulonglong2* row = (const ulonglong2*)tl[tk];
            unsigned long long a0 = 0ull, a1 = 0ull;
            #pragma unroll
            for (int i = 0; i < 16; i++) {
                ulonglong2 k = row[s + 8 * i];
                fma2(a0, q[i].x, k.x);
                fma2(a1, q[i].y, k.y);
            }
            { ulonglong2 k = row[128 + s];     fma2(a0, q[16].x, k.x); fma2(a1, q[16].y, k.y); }
            { ulonglong2 k = row[128 + s + 8]; fma2(a0, q[17].x, k.x); fma2(a1, q[17].y, k.y); }
            float2 f0 = u2f(a0), f1 = u2f(a1);
            float sc = (f0.x + f0.y) + (f1.x + f1.y);
            sc += __shfl_xor_sync(0xffffffffu, sc, 1);
            sc += __shfl_xor_sync(0xffffffffu, sc, 2);
            sc += __shfl_xor_sync(0xffffffffu, sc, 4);
            sc *= SCALE_;
            if (sc > m) {                       // lazy rescale (rare)
                float corr = __expf(m - sc);
                m = sc;
                l *= corr;
                unsigned long long c2 = f2u(corr, corr);
                #pragma unroll
                for (int i = 0; i < 32; i++) acc[i] = mul2(acc[i], c2);
            }
            float p = __expf(sc - m);
            l += p;
            unsigned long long p2 = f2u(p, p);
            #pragma unroll
            for (int i = 0; i < 16; i++) {
                ulonglong2 v = row[s + 8 * i];
                fma2(acc[2 * i],     p2, v.x);
                fma2(acc[2 * i + 1], p2, v.y);
            }
        }
        __syncthreads();
    }
    float4* dst = (float4*)(g_pout + ((size_t)(b * NSPLIT + split) * H_ + head) * KVLR_);
    #pragma unroll
    for (int i = 0; i < 16; i++) {
        float2 lo = u2f(acc[2 * i]), hi = u2f(acc[2 * i + 1]);
        dst[s + 8 * i] = make_float4(lo.x, lo.y, hi.x, hi.y);
    }
    if (s == 0) {
        float* ml = g_pml + ((b * NSPLIT + split) * H_ + head) * 2;
        ml[0] = m;
        ml[1] = l;
    }
}

// ---------------- combine split partials (log-sum-exp merge) ----------------
__global__ void combine_kernel() {
    int h = blockIdx.x, b = blockIdx.y, tid = threadIdx.x;  // 128 threads
    const float* mlb = g_pml + (b * NSPLIT * H_ + h) * 2;
    float M = -INFINITY;
    for (int sp = 0; sp < NSPLIT; sp++) M = fmaxf(M, mlb[sp * H_ * 2]);
    float L = 0.f;
    float acc[4] = {0.f, 0.f, 0.f, 0.f};
    for (int sp = 0; sp < NSPLIT; sp++) {
        float e = __expf(mlb[sp * H_ * 2] - M);
        L += mlb[sp * H_ * 2 + 1] * e;
        const float* pp = g_pout + ((size_t)(b * NSPLIT + sp) * H_ + h) * KVLR_;
        #pragma unroll
        for (int k = 0; k < 4; k++) acc[k] += e * pp[tid + 128 * k];
    }
    float inv = 1.0f / L;
    #pragma unroll
    for (int k = 0; k < 4; k++)
        g_ctx[(size_t)(b * H_ + h) * KVLR_ + tid + 128 * k] = acc[k] * inv;
}

// ---------------- output projection through W_uv: ctxv[b][h*128+d] = ctx[b][h]·W_uv[h][d] ----------------
__global__ void uv_kernel(const float* __restrict__ wkvb) {
    __shared__ __align__(16) float cs[KVLR_];
    int h = blockIdx.x, b = blockIdx.y, tid = threadIdx.x;  // 128 threads
    for (int i = tid; i < KVLR_; i += 128) cs[i] = g_ctx[(size_t)(b * H_ + h) * KVLR_ + i];
    __syncthreads();
    int w = tid >> 5, lane = tid & 31;
    const ulonglong2* cs2 = (const ulonglong2*)cs;
    for (int k = 0; k < 32; k++) {
        int d = w * 32 + k;
        const ulonglong2* wr = (const ulonglong2*)(wkvb + ((size_t)(h * 256 + DN_ + d)) * KVLR_);
        unsigned long long a0 = 0ull, a1 = 0ull;
        #pragma unroll
        for (int j = lane; j < 128; j += 32) {
            ulonglong2 wv = __ldg(wr + j);
            ulonglong2 xv = cs2[j];
            fma2(a0, wv.x, xv.x);
            fma2(a1, wv.y, xv.y);
        }
        float2 f0 = u2f(a0), f1 = u2f(a1);
        float a = (f0.x + f0.y) + (f1.x + f1.y);
        #pragma unroll
        for (int off = 16; off; off >>= 1) a += __shfl_xor_sync(0xffffffffu, a, off);
        if (lane == 0) g_ctxv[b * DIM_ + h * DV_ + d] = a;
    }
}

// ---------------- launch ----------------
extern "C" void kernel_launch(void* const* d_in, const int* in_sizes, int n_in,
                              void* d_out, int out_size) {
    const float* x     = (const float*)d_in[0];
    // d_in[1] = start_pos (compile-time constant 8191)
    const float* fcos  = (const float*)d_in[2];
    const float* fsin  = (const float*)d_in[3];
    const float* kvpre = (const float*)d_in[4];
    const float* pepre = (const float*)d_in[5];
    const float* wqa   = (const float*)d_in[6];
    const float* wqab  = (const float*)d_in[7];
    const float* qnw   = (const float*)d_in[8];
    const float* wqb   = (const float*)d_in[9];
    const float* wqbb  = (const float*)d_in[10];
    const float* wkva  = (const float*)d_in[11];
    const float* wkvab = (const float*)d_in[12];
    const float* kvnw  = (const float*)d_in[13];
    const float* wkvb  = (const float*)d_in[14];
    const float* wo    = (const float*)d_in[15];
    const float* wob   = (const float*)d_in[16];
    float* out = (float*)d_out;

    matvec8<<<576 / 8, 256>>>(wkva, wkvab, x, nullptr, 0, 1, 576, DIM_);        // kvpe
    matvec8<<<QLR_ / 8, 256>>>(wqa, wqab, x, nullptr, 0, 2, QLR_, DIM_);        // q_a raw
    rmsq_kernel<<<B_, 256>>>(qnw);
    kvprep_kernel<<<B_, 256>>>(kvnw, fcos, fsin);
    matvec8<<<3072 / 8, 256>>>(wqb, wqbb, nullptr, nullptr, 1, 3, 3072, QLR_);  // q
    qprep_kernel<<<dim3(H_, B_), 512>>>(wkvb, fcos, fsin);
    attn_kernel<<<dim3(NSPLIT, B_), 128>>>(kvpre, pepre);
    combine_kernel<<<dim3(H_, B_), 128>>>();
    uv_kernel<<<dim3(H_, B_), 128>>>(wkvb);
    matvec8<<<DIM_ / 8, 256>>>(wo, wob, nullptr, out, 2, 0, DIM_, DIM_);        // final
}